// round 3
// baseline (speedup 1.0000x reference)
#include <cuda_runtime.h>

// LSTM featurizer: T=1024 steps, B=64, V=256, E=256, H=1024.
// Persistent kernel: 128 CTAs (one per SM), each CTA owns 8 hidden columns
// (=> 32 gate rows: i/f/g/o x 8). W_hh slice (128KB) and Gx lookup table slice
// (32KB) live in SMEM for the whole run. h ping-pongs in gmem (L2-resident),
// steps separated by a sense-reversing grid barrier.

static constexpr int T_STEPS = 1024;
static constexpr int NB      = 64;    // batch
static constexpr int NV      = 256;   // vocab
static constexpr int NE      = 256;   // embed dim
static constexpr int NH      = 1024;  // hidden
static constexpr int NCTA    = 128;
static constexpr int NTHR    = 128;

typedef unsigned long long ull;

__device__ float    g_h[2][NB][NH];   // ping-pong hidden state
__device__ unsigned g_epoch;          // zero-init at module load
__device__ unsigned g_count;

// ---- packed f32x2 FMA (Blackwell FFMA2) ----
__device__ __forceinline__ void fma2(ull& acc, ull a, ull b) {
    asm("fma.rn.f32x2 %0, %1, %2, %0;" : "+l"(acc) : "l"(a), "l"(b));
}
__device__ __forceinline__ float2 unpack2(ull v) {
    float2 r;
    asm("mov.b64 {%0, %1}, %2;" : "=f"(r.x), "=f"(r.y) : "l"(v));
    return r;
}
__device__ __forceinline__ float fast_sigmoid(float x) {
    return __fdividef(1.f, 1.f + __expf(-x));
}
__device__ __forceinline__ float fast_tanh(float x) {
    x = fmaxf(x, -44.f);                 // keep __expf finite (avoid inf/inf)
    float e = __expf(-2.f * x);
    return __fdividef(1.f - e, 1.f + e);
}

__device__ __forceinline__ void grid_barrier() {
    __syncthreads();
    if (threadIdx.x == 0) {
        unsigned e = *((volatile unsigned*)&g_epoch);
        unsigned a = atomicAdd(&g_count, 1);
        if (a == NCTA - 1) {
            *((volatile unsigned*)&g_count) = 0;
            __threadfence();
            atomicAdd(&g_epoch, 1);
        } else {
            while (*((volatile unsigned*)&g_epoch) == e) { __nanosleep(64); }
        }
    }
    __syncthreads();
}

// SMEM layout (floats):
//   W_s   : 32*1024 + 16   (row r at r*1024 + (r>>3)*4 -> conflict-free 16B LDS)
//   Gx_s  : 256*32
//   psum  : 4*64*32        (reused as W_ih^T staging in prologue)
//   c_s   : 512, lc_s : 512, tok_s : 64 (int), sl_s : 64 (int)
static constexpr int W_S_FLOATS  = 32 * 1024 + 16;
static constexpr int GX_FLOATS   = NV * 32;
static constexpr int PSUM_FLOATS = 4 * NB * 32;
static constexpr int SMEM_FLOATS = W_S_FLOATS + GX_FLOATS + PSUM_FLOATS + 512 + 512 + 128;
static constexpr int SMEM_BYTES  = SMEM_FLOATS * 4;

__global__ void __launch_bounds__(NTHR, 1)
lstm_persistent(const int* __restrict__ tokens, const int* __restrict__ seq_len,
                const float* __restrict__ emb, const float* __restrict__ W_ih,
                const float* __restrict__ W_hh, const float* __restrict__ b_ih,
                const float* __restrict__ b_hh, float* __restrict__ out)
{
    extern __shared__ float smem[];
    float* W_s   = smem;
    float* Gx_s  = W_s  + W_S_FLOATS;
    float* psum  = Gx_s + GX_FLOATS;      // also W_ih^T staging in prologue
    float* c_s   = psum + PSUM_FLOATS;
    float* lc_s  = c_s  + 512;
    int*   tok_s = (int*)(lc_s + 512);
    int*   sl_s  = tok_s + 64;

    const int tid  = threadIdx.x;
    const int cta  = blockIdx.x;
    const int j0   = cta * 8;             // this CTA's hidden columns [j0, j0+8)
    const int warp = tid >> 5;
    const int lane = tid & 31;

    // ---------------- prologue ----------------
    // 1) W_hh slice -> SMEM (rows r=0..31: gate=r>>3, col=r&7)
    for (int idx = tid; idx < 32 * NH; idx += NTHR) {
        int r = idx >> 10, k = idx & 1023;
        int grow = (r >> 3) * NH + j0 + (r & 7);
        W_s[r * 1024 + (r >> 3) * 4 + k] = W_hh[grow * NH + k];
    }
    // 2) W_ih^T slice -> psum area: [e][32]
    for (int idx = tid; idx < 32 * NE; idx += NTHR) {
        int r = idx >> 8, e = idx & 255;
        int grow = (r >> 3) * NH + j0 + (r & 7);
        psum[e * 32 + r] = W_ih[grow * NE + e];
    }
    // 3) zero h0 slice + local cell state; stage seq_len
    for (int idx = tid; idx < NB * 8; idx += NTHR) {
        int b = idx >> 3, col = idx & 7;
        g_h[0][b][j0 + col] = 0.f;
        c_s[idx]  = 0.f;
        lc_s[idx] = 0.f;
    }
    if (tid < NB) sl_s[tid] = seq_len[tid];
    __syncthreads();

    // 4) Gx[v][r] = b_ih+b_hh + emb[v] . W_ih[row(r)]  (warp w: v = w,w+4,..., lane = r)
    {
        int grow   = (lane >> 3) * NH + j0 + (lane & 7);
        float bias = b_ih[grow] + b_hh[grow];
        for (int v = warp; v < NV; v += 4) {
            const float4* ev = (const float4*)(emb + v * NE);
            float s = 0.f;
            #pragma unroll 8
            for (int e4 = 0; e4 < NE / 4; ++e4) {
                float4 e = __ldg(ev + e4);
                int eb = e4 * 4;
                s += e.x * psum[(eb + 0) * 32 + lane];
                s += e.y * psum[(eb + 1) * 32 + lane];
                s += e.z * psum[(eb + 2) * 32 + lane];
                s += e.w * psum[(eb + 3) * 32 + lane];
            }
            Gx_s[v * 32 + lane] = s + bias;
        }
    }
    __threadfence();
    grid_barrier();

    // ---------------- main recurrence ----------------
    // thread tile: 8 batches (bg) x 8 gate rows (rg), warp owns k-slice of 256
    const int bg = lane >> 2;
    const int rg = lane & 3;
    const int kbase = warp * 256;

    for (int t = 0; t < T_STEPS; ++t) {
        const float* hp = &g_h[t & 1][0][0];
        float*       hn = &g_h[(t + 1) & 1][0][0];
        if (tid < NB) tok_s[tid] = tokens[t * NB + tid];

        ull acc[8][8];
        #pragma unroll
        for (int i = 0; i < 8; ++i)
            #pragma unroll
            for (int j = 0; j < 8; ++j) acc[i][j] = 0ull;

        const float* hbase = hp  + (bg * 8) * NH + kbase;
        const float* wbase = W_s + (rg * 8) * 1024 + rg * 4 + kbase;

        longlong2 ha[8], hb[8];
        #pragma unroll
        for (int i = 0; i < 8; ++i)
            ha[i] = __ldcg((const longlong2*)(hbase + i * NH));

        #pragma unroll 1
        for (int k4 = 0; k4 < 64; k4 += 2) {
            #pragma unroll
            for (int i = 0; i < 8; ++i)
                hb[i] = __ldcg((const longlong2*)(hbase + i * NH + (k4 + 1) * 4));
            #pragma unroll
            for (int j = 0; j < 8; ++j) {
                longlong2 wv = *(const longlong2*)(wbase + j * 1024 + k4 * 4);
                #pragma unroll
                for (int i = 0; i < 8; ++i) {
                    fma2(acc[i][j], (ull)ha[i].x, (ull)wv.x);
                    fma2(acc[i][j], (ull)ha[i].y, (ull)wv.y);
                }
            }
            if (k4 + 2 < 64) {
                #pragma unroll
                for (int i = 0; i < 8; ++i)
                    ha[i] = __ldcg((const longlong2*)(hbase + i * NH + (k4 + 2) * 4));
            }
            #pragma unroll
            for (int j = 0; j < 8; ++j) {
                longlong2 wv = *(const longlong2*)(wbase + j * 1024 + (k4 + 1) * 4);
                #pragma unroll
                for (int i = 0; i < 8; ++i) {
                    fma2(acc[i][j], (ull)hb[i].x, (ull)wv.x);
                    fma2(acc[i][j], (ull)hb[i].y, (ull)wv.y);
                }
            }
        }

        // partial sums -> SMEM
        #pragma unroll
        for (int i = 0; i < 8; ++i) {
            int b = bg * 8 + i;
            #pragma unroll
            for (int j = 0; j < 8; ++j) {
                float2 f = unpack2(acc[i][j]);
                psum[warp * 2048 + b * 32 + rg * 8 + j] = f.x + f.y;
            }
        }
        __syncthreads();

        // reduce across 4 k-slice warps + gate nonlinearities; 4 (b,col) per thread
        #pragma unroll
        for (int q = 0; q < 4; ++q) {
            int idx = q * NTHR + tid;
            int b = idx >> 3, col = idx & 7;
            float gi = 0.f, gf = 0.f, gg = 0.f, go = 0.f;
            #pragma unroll
            for (int w = 0; w < 4; ++w) {
                const float* pp = psum + w * 2048 + b * 32 + col;
                gi += pp[0]; gf += pp[8]; gg += pp[16]; go += pp[24];
            }
            const float* gx = Gx_s + tok_s[b] * 32 + col;
            gi += gx[0]; gf += gx[8]; gg += gx[16]; go += gx[24];

            float c_old = c_s[idx];
            float cn = fast_sigmoid(gf) * c_old + fast_sigmoid(gi) * fast_tanh(gg);
            float hv = fast_sigmoid(go) * fast_tanh(cn);
            c_s[idx] = cn;
            if ((t == 0) || (t < sl_s[b])) lc_s[idx] = cn;
            hn[b * NH + j0 + col] = hv;
        }
        __threadfence();
        grid_barrier();
    }

    // ---------------- epilogue: emit last_c ----------------
    #pragma unroll
    for (int q = 0; q < 4; ++q) {
        int idx = q * NTHR + tid;
        int b = idx >> 3, col = idx & 7;
        out[b * NH + j0 + col] = lc_s[idx];
    }
}

extern "C" void kernel_launch(void* const* d_in, const int* in_sizes, int n_in,
                              void* d_out, int out_size)
{
    const int*   tokens = (const int*)d_in[0];
    const int*   seqlen = (const int*)d_in[1];
    const float* emb    = (const float*)d_in[2];
    const float* W_ih   = (const float*)d_in[3];
    const float* W_hh   = (const float*)d_in[4];
    const float* b_ih   = (const float*)d_in[5];
    const float* b_hh   = (const float*)d_in[6];
    float*       out    = (float*)d_out;

    cudaFuncSetAttribute(lstm_persistent,
                         cudaFuncAttributeMaxDynamicSharedMemorySize, SMEM_BYTES);
    lstm_persistent<<<NCTA, NTHR, SMEM_BYTES>>>(tokens, seqlen, emb, W_ih, W_hh,
                                                b_ih, b_hh, out);
}

// round 6
// speedup vs baseline: 1.0391x; 1.0391x over previous
#include <cuda_runtime.h>

// LSTM featurizer: T=1024 steps, B=64, V=256, E=256, H=1024.
// Persistent kernel: 128 CTAs (one per SM), each CTA owns 8 hidden columns
// (=> 32 gate rows: i/f/g/o x 8). W_hh slice (128KB) and Gx lookup table slice
// (32KB) live in SMEM for the whole run. h ping-pongs in gmem (L2-resident),
// steps separated by a sense-reversing grid barrier.

static constexpr int T_STEPS = 1024;
static constexpr int NB      = 64;    // batch
static constexpr int NV      = 256;   // vocab
static constexpr int NE      = 256;   // embed dim
static constexpr int NH      = 1024;  // hidden
static constexpr int NCTA    = 128;
static constexpr int NTHR    = 128;

typedef unsigned long long ull;

__device__ float    g_h[2][NB][NH];   // ping-pong hidden state
__device__ unsigned g_epoch;          // zero-init at module load
__device__ unsigned g_count;

// ---- packed f32x2 FMA (Blackwell FFMA2) ----
__device__ __forceinline__ void fma2(ull& acc, ull a, ull b) {
    asm("fma.rn.f32x2 %0, %1, %2, %0;" : "+l"(acc) : "l"(a), "l"(b));
}
__device__ __forceinline__ float2 unpack2(ull v) {
    float2 r;
    asm("mov.b64 {%0, %1}, %2;" : "=f"(r.x), "=f"(r.y) : "l"(v));
    return r;
}
__device__ __forceinline__ float fast_sigmoid(float x) {
    return __fdividef(1.f, 1.f + __expf(-x));
}
__device__ __forceinline__ float fast_tanh(float x) {
    x = fmaxf(x, -44.f);                 // keep __expf finite (avoid inf/inf)
    float e = __expf(-2.f * x);
    return __fdividef(1.f - e, 1.f + e);
}

__device__ __forceinline__ void grid_barrier() {
    __syncthreads();
    if (threadIdx.x == 0) {
        unsigned e = *((volatile unsigned*)&g_epoch);
        unsigned a = atomicAdd(&g_count, 1);
        if (a == NCTA - 1) {
            *((volatile unsigned*)&g_count) = 0;
            __threadfence();
            atomicAdd(&g_epoch, 1);
        } else {
            while (*((volatile unsigned*)&g_epoch) == e) { __nanosleep(64); }
        }
    }
    __syncthreads();
}

// SMEM layout (floats):
//   W_s   : 32*1024 + 16   (row r at r*1024 + (r>>3)*4 -> conflict-free 16B LDS)
//   Gx_s  : 256*32
//   psum  : 4*64*32        (reused as W_ih^T staging in prologue)
//   c_s   : 512, lc_s : 512, tok_s : 64 (int), sl_s : 64 (int)
static constexpr int W_S_FLOATS  = 32 * 1024 + 16;
static constexpr int GX_FLOATS   = NV * 32;
static constexpr int PSUM_FLOATS = 4 * NB * 32;
static constexpr int SMEM_FLOATS = W_S_FLOATS + GX_FLOATS + PSUM_FLOATS + 512 + 512 + 128;
static constexpr int SMEM_BYTES  = SMEM_FLOATS * 4;

__global__ void __launch_bounds__(NTHR, 1)
lstm_persistent(const int* __restrict__ tokens, const int* __restrict__ seq_len,
                const float* __restrict__ emb, const float* __restrict__ W_ih,
                const float* __restrict__ W_hh, const float* __restrict__ b_ih,
                const float* __restrict__ b_hh, float* __restrict__ out)
{
    extern __shared__ float smem[];
    float* W_s   = smem;
    float* Gx_s  = W_s  + W_S_FLOATS;
    float* psum  = Gx_s + GX_FLOATS;      // also W_ih^T staging in prologue
    float* c_s   = psum + PSUM_FLOATS;
    float* lc_s  = c_s  + 512;
    int*   tok_s = (int*)(lc_s + 512);
    int*   sl_s  = tok_s + 64;

    const int tid  = threadIdx.x;
    const int cta  = blockIdx.x;
    const int j0   = cta * 8;             // this CTA's hidden columns [j0, j0+8)
    const int warp = tid >> 5;
    const int lane = tid & 31;

    // ---------------- prologue ----------------
    // 1) W_hh slice -> SMEM (rows r=0..31: gate=r>>3, col=r&7)
    for (int idx = tid; idx < 32 * NH; idx += NTHR) {
        int r = idx >> 10, k = idx & 1023;
        int grow = (r >> 3) * NH + j0 + (r & 7);
        W_s[r * 1024 + (r >> 3) * 4 + k] = W_hh[grow * NH + k];
    }
    // 2) W_ih^T slice -> psum area: [e][32]
    for (int idx = tid; idx < 32 * NE; idx += NTHR) {
        int r = idx >> 8, e = idx & 255;
        int grow = (r >> 3) * NH + j0 + (r & 7);
        psum[e * 32 + r] = W_ih[grow * NE + e];
    }
    // 3) zero h0 slice + local cell state; stage seq_len
    for (int idx = tid; idx < NB * 8; idx += NTHR) {
        int b = idx >> 3, col = idx & 7;
        g_h[0][b][j0 + col] = 0.f;
        c_s[idx]  = 0.f;
        lc_s[idx] = 0.f;
    }
    if (tid < NB) sl_s[tid] = seq_len[tid];
    __syncthreads();

    // 4) Gx[v][r] = b_ih+b_hh + emb[v] . W_ih[row(r)]  (warp w: v = w,w+4,..., lane = r)
    {
        int grow   = (lane >> 3) * NH + j0 + (lane & 7);
        float bias = b_ih[grow] + b_hh[grow];
        for (int v = warp; v < NV; v += 4) {
            const float4* ev = (const float4*)(emb + v * NE);
            float s = 0.f;
            #pragma unroll 8
            for (int e4 = 0; e4 < NE / 4; ++e4) {
                float4 e = __ldg(ev + e4);
                int eb = e4 * 4;
                s += e.x * psum[(eb + 0) * 32 + lane];
                s += e.y * psum[(eb + 1) * 32 + lane];
                s += e.z * psum[(eb + 2) * 32 + lane];
                s += e.w * psum[(eb + 3) * 32 + lane];
            }
            Gx_s[v * 32 + lane] = s + bias;
        }
    }
    __threadfence();
    grid_barrier();

    // ---------------- main recurrence ----------------
    // thread tile: 8 batches (bg) x 8 gate rows (rg), warp owns k-slice of 256
    const int bg = lane >> 2;
    const int rg = lane & 3;
    const int kbase = warp * 256;

    for (int t = 0; t < T_STEPS; ++t) {
        const float* hp = &g_h[t & 1][0][0];
        float*       hn = &g_h[(t + 1) & 1][0][0];
        if (tid < NB) tok_s[tid] = tokens[t * NB + tid];

        ull acc[8][8];
        #pragma unroll
        for (int i = 0; i < 8; ++i)
            #pragma unroll
            for (int j = 0; j < 8; ++j) acc[i][j] = 0ull;

        const float* hbase = hp  + (bg * 8) * NH + kbase;
        const float* wbase = W_s + (rg * 8) * 1024 + rg * 4 + kbase;

        longlong2 ha[8], hb[8];
        #pragma unroll
        for (int i = 0; i < 8; ++i)
            ha[i] = __ldcg((const longlong2*)(hbase + i * NH));

        #pragma unroll 1
        for (int k4 = 0; k4 < 64; k4 += 2) {
            #pragma unroll
            for (int i = 0; i < 8; ++i)
                hb[i] = __ldcg((const longlong2*)(hbase + i * NH + (k4 + 1) * 4));
            #pragma unroll
            for (int j = 0; j < 8; ++j) {
                longlong2 wv = *(const longlong2*)(wbase + j * 1024 + k4 * 4);
                #pragma unroll
                for (int i = 0; i < 8; ++i) {
                    fma2(acc[i][j], (ull)ha[i].x, (ull)wv.x);
                    fma2(acc[i][j], (ull)ha[i].y, (ull)wv.y);
                }
            }
            if (k4 + 2 < 64) {
                #pragma unroll
                for (int i = 0; i < 8; ++i)
                    ha[i] = __ldcg((const longlong2*)(hbase + i * NH + (k4 + 2) * 4));
            }
            #pragma unroll
            for (int j = 0; j < 8; ++j) {
                longlong2 wv = *(const longlong2*)(wbase + j * 1024 + (k4 + 1) * 4);
                #pragma unroll
                for (int i = 0; i < 8; ++i) {
                    fma2(acc[i][j], (ull)hb[i].x, (ull)wv.x);
                    fma2(acc[i][j], (ull)hb[i].y, (ull)wv.y);
                }
            }
        }

        // partial sums -> SMEM
        #pragma unroll
        for (int i = 0; i < 8; ++i) {
            int b = bg * 8 + i;
            #pragma unroll
            for (int j = 0; j < 8; ++j) {
                float2 f = unpack2(acc[i][j]);
                psum[warp * 2048 + b * 32 + rg * 8 + j] = f.x + f.y;
            }
        }
        __syncthreads();

        // reduce across 4 k-slice warps + gate nonlinearities; 4 (b,col) per thread
        #pragma unroll
        for (int q = 0; q < 4; ++q) {
            int idx = q * NTHR + tid;
            int b = idx >> 3, col = idx & 7;
            float gi = 0.f, gf = 0.f, gg = 0.f, go = 0.f;
            #pragma unroll
            for (int w = 0; w < 4; ++w) {
                const float* pp = psum + w * 2048 + b * 32 + col;
                gi += pp[0]; gf += pp[8]; gg += pp[16]; go += pp[24];
            }
            const float* gx = Gx_s + tok_s[b] * 32 + col;
            gi += gx[0]; gf += gx[8]; gg += gx[16]; go += gx[24];

            float c_old = c_s[idx];
            float cn = fast_sigmoid(gf) * c_old + fast_sigmoid(gi) * fast_tanh(gg);
            float hv = fast_sigmoid(go) * fast_tanh(cn);
            c_s[idx] = cn;
            if ((t == 0) || (t < sl_s[b])) lc_s[idx] = cn;
            hn[b * NH + j0 + col] = hv;
        }
        __threadfence();
        grid_barrier();
    }

    // ---------------- epilogue: emit last_c ----------------
    #pragma unroll
    for (int q = 0; q < 4; ++q) {
        int idx = q * NTHR + tid;
        int b = idx >> 3, col = idx & 7;
        out[b * NH + j0 + col] = lc_s[idx];
    }
}

extern "C" void kernel_launch(void* const* d_in, const int* in_sizes, int n_in,
                              void* d_out, int out_size)
{
    const int*   tokens = (const int*)d_in[0];
    const int*   seqlen = (const int*)d_in[1];
    const float* emb    = (const float*)d_in[2];
    const float* W_ih   = (const float*)d_in[3];
    const float* W_hh   = (const float*)d_in[4];
    const float* b_ih   = (const float*)d_in[5];
    const float* b_hh   = (const float*)d_in[6];
    float*       out    = (float*)d_out;

    cudaFuncSetAttribute(lstm_persistent,
                         cudaFuncAttributeMaxDynamicSharedMemorySize, SMEM_BYTES);
    lstm_persistent<<<NCTA, NTHR, SMEM_BYTES>>>(tokens, seqlen, emb, W_ih, W_hh,
                                                b_ih, b_hh, out);
}

// round 7
// speedup vs baseline: 1.0419x; 1.0027x over previous
#include <cuda_runtime.h>

// LSTM featurizer: T=1024 steps, B=64, V=256, E=256, H=1024.
// Persistent kernel: 128 CTAs (one per SM), each CTA owns 8 hidden columns
// (=> 32 gate rows: i/f/g/o x 8). W_hh slice (128KB) and Gx lookup table slice
// (32KB) live in SMEM for the whole run. h ping-pongs in gmem (L2-resident),
// steps separated by a sense-reversing grid barrier.

static constexpr int T_STEPS = 1024;
static constexpr int NB      = 64;    // batch
static constexpr int NV      = 256;   // vocab
static constexpr int NE      = 256;   // embed dim
static constexpr int NH      = 1024;  // hidden
static constexpr int NCTA    = 128;
static constexpr int NTHR    = 128;

typedef unsigned long long ull;

__device__ float    g_h[2][NB][NH];   // ping-pong hidden state
__device__ unsigned g_epoch;          // zero-init at module load
__device__ unsigned g_count;

// ---- packed f32x2 FMA (Blackwell FFMA2) ----
__device__ __forceinline__ void fma2(ull& acc, ull a, ull b) {
    asm("fma.rn.f32x2 %0, %1, %2, %0;" : "+l"(acc) : "l"(a), "l"(b));
}
__device__ __forceinline__ float2 unpack2(ull v) {
    float2 r;
    asm("mov.b64 {%0, %1}, %2;" : "=f"(r.x), "=f"(r.y) : "l"(v));
    return r;
}
__device__ __forceinline__ float fast_sigmoid(float x) {
    return __fdividef(1.f, 1.f + __expf(-x));
}
__device__ __forceinline__ float fast_tanh(float x) {
    x = fmaxf(x, -44.f);                 // keep __expf finite (avoid inf/inf)
    float e = __expf(-2.f * x);
    return __fdividef(1.f - e, 1.f + e);
}

__device__ __forceinline__ void grid_barrier() {
    __syncthreads();
    if (threadIdx.x == 0) {
        unsigned e = *((volatile unsigned*)&g_epoch);
        unsigned a = atomicAdd(&g_count, 1);
        if (a == NCTA - 1) {
            *((volatile unsigned*)&g_count) = 0;
            __threadfence();
            atomicAdd(&g_epoch, 1);
        } else {
            while (*((volatile unsigned*)&g_epoch) == e) { __nanosleep(64); }
        }
    }
    __syncthreads();
}

// SMEM layout (floats):
//   W_s   : 32*1024 + 16   (row r at r*1024 + (r>>3)*4 -> conflict-free 16B LDS)
//   Gx_s  : 256*32
//   psum  : 4*64*32        (reused as W_ih^T staging in prologue)
//   c_s   : 512, lc_s : 512, tok_s : 64 (int), sl_s : 64 (int)
static constexpr int W_S_FLOATS  = 32 * 1024 + 16;
static constexpr int GX_FLOATS   = NV * 32;
static constexpr int PSUM_FLOATS = 4 * NB * 32;
static constexpr int SMEM_FLOATS = W_S_FLOATS + GX_FLOATS + PSUM_FLOATS + 512 + 512 + 128;
static constexpr int SMEM_BYTES  = SMEM_FLOATS * 4;

__global__ void __launch_bounds__(NTHR, 1)
lstm_persistent(const int* __restrict__ tokens, const int* __restrict__ seq_len,
                const float* __restrict__ emb, const float* __restrict__ W_ih,
                const float* __restrict__ W_hh, const float* __restrict__ b_ih,
                const float* __restrict__ b_hh, float* __restrict__ out)
{
    extern __shared__ float smem[];
    float* W_s   = smem;
    float* Gx_s  = W_s  + W_S_FLOATS;
    float* psum  = Gx_s + GX_FLOATS;      // also W_ih^T staging in prologue
    float* c_s   = psum + PSUM_FLOATS;
    float* lc_s  = c_s  + 512;
    int*   tok_s = (int*)(lc_s + 512);
    int*   sl_s  = tok_s + 64;

    const int tid  = threadIdx.x;
    const int cta  = blockIdx.x;
    const int j0   = cta * 8;             // this CTA's hidden columns [j0, j0+8)
    const int warp = tid >> 5;
    const int lane = tid & 31;

    // ---------------- prologue ----------------
    // 1) W_hh slice -> SMEM (rows r=0..31: gate=r>>3, col=r&7)
    for (int idx = tid; idx < 32 * NH; idx += NTHR) {
        int r = idx >> 10, k = idx & 1023;
        int grow = (r >> 3) * NH + j0 + (r & 7);
        W_s[r * 1024 + (r >> 3) * 4 + k] = W_hh[grow * NH + k];
    }
    // 2) W_ih^T slice -> psum area: [e][32]
    for (int idx = tid; idx < 32 * NE; idx += NTHR) {
        int r = idx >> 8, e = idx & 255;
        int grow = (r >> 3) * NH + j0 + (r & 7);
        psum[e * 32 + r] = W_ih[grow * NE + e];
    }
    // 3) zero h0 slice + local cell state; stage seq_len
    for (int idx = tid; idx < NB * 8; idx += NTHR) {
        int b = idx >> 3, col = idx & 7;
        g_h[0][b][j0 + col] = 0.f;
        c_s[idx]  = 0.f;
        lc_s[idx] = 0.f;
    }
    if (tid < NB) sl_s[tid] = seq_len[tid];
    __syncthreads();

    // 4) Gx[v][r] = b_ih+b_hh + emb[v] . W_ih[row(r)]  (warp w: v = w,w+4,..., lane = r)
    {
        int grow   = (lane >> 3) * NH + j0 + (lane & 7);
        float bias = b_ih[grow] + b_hh[grow];
        for (int v = warp; v < NV; v += 4) {
            const float4* ev = (const float4*)(emb + v * NE);
            float s = 0.f;
            #pragma unroll 8
            for (int e4 = 0; e4 < NE / 4; ++e4) {
                float4 e = __ldg(ev + e4);
                int eb = e4 * 4;
                s += e.x * psum[(eb + 0) * 32 + lane];
                s += e.y * psum[(eb + 1) * 32 + lane];
                s += e.z * psum[(eb + 2) * 32 + lane];
                s += e.w * psum[(eb + 3) * 32 + lane];
            }
            Gx_s[v * 32 + lane] = s + bias;
        }
    }
    __threadfence();
    grid_barrier();

    // ---------------- main recurrence ----------------
    // thread tile: 8 batches (bg) x 8 gate rows (rg), warp owns k-slice of 256
    const int bg = lane >> 2;
    const int rg = lane & 3;
    const int kbase = warp * 256;

    for (int t = 0; t < T_STEPS; ++t) {
        const float* hp = &g_h[t & 1][0][0];
        float*       hn = &g_h[(t + 1) & 1][0][0];
        if (tid < NB) tok_s[tid] = tokens[t * NB + tid];

        ull acc[8][8];
        #pragma unroll
        for (int i = 0; i < 8; ++i)
            #pragma unroll
            for (int j = 0; j < 8; ++j) acc[i][j] = 0ull;

        const float* hbase = hp  + (bg * 8) * NH + kbase;
        const float* wbase = W_s + (rg * 8) * 1024 + rg * 4 + kbase;

        longlong2 ha[8], hb[8];
        #pragma unroll
        for (int i = 0; i < 8; ++i)
            ha[i] = __ldcg((const longlong2*)(hbase + i * NH));

        #pragma unroll 1
        for (int k4 = 0; k4 < 64; k4 += 2) {
            #pragma unroll
            for (int i = 0; i < 8; ++i)
                hb[i] = __ldcg((const longlong2*)(hbase + i * NH + (k4 + 1) * 4));
            #pragma unroll
            for (int j = 0; j < 8; ++j) {
                longlong2 wv = *(const longlong2*)(wbase + j * 1024 + k4 * 4);
                #pragma unroll
                for (int i = 0; i < 8; ++i) {
                    fma2(acc[i][j], (ull)ha[i].x, (ull)wv.x);
                    fma2(acc[i][j], (ull)ha[i].y, (ull)wv.y);
                }
            }
            if (k4 + 2 < 64) {
                #pragma unroll
                for (int i = 0; i < 8; ++i)
                    ha[i] = __ldcg((const longlong2*)(hbase + i * NH + (k4 + 2) * 4));
            }
            #pragma unroll
            for (int j = 0; j < 8; ++j) {
                longlong2 wv = *(const longlong2*)(wbase + j * 1024 + (k4 + 1) * 4);
                #pragma unroll
                for (int i = 0; i < 8; ++i) {
                    fma2(acc[i][j], (ull)hb[i].x, (ull)wv.x);
                    fma2(acc[i][j], (ull)hb[i].y, (ull)wv.y);
                }
            }
        }

        // partial sums -> SMEM
        #pragma unroll
        for (int i = 0; i < 8; ++i) {
            int b = bg * 8 + i;
            #pragma unroll
            for (int j = 0; j < 8; ++j) {
                float2 f = unpack2(acc[i][j]);
                psum[warp * 2048 + b * 32 + rg * 8 + j] = f.x + f.y;
            }
        }
        __syncthreads();

        // reduce across 4 k-slice warps + gate nonlinearities; 4 (b,col) per thread
        #pragma unroll
        for (int q = 0; q < 4; ++q) {
            int idx = q * NTHR + tid;
            int b = idx >> 3, col = idx & 7;
            float gi = 0.f, gf = 0.f, gg = 0.f, go = 0.f;
            #pragma unroll
            for (int w = 0; w < 4; ++w) {
                const float* pp = psum + w * 2048 + b * 32 + col;
                gi += pp[0]; gf += pp[8]; gg += pp[16]; go += pp[24];
            }
            const float* gx = Gx_s + tok_s[b] * 32 + col;
            gi += gx[0]; gf += gx[8]; gg += gx[16]; go += gx[24];

            float c_old = c_s[idx];
            float cn = fast_sigmoid(gf) * c_old + fast_sigmoid(gi) * fast_tanh(gg);
            float hv = fast_sigmoid(go) * fast_tanh(cn);
            c_s[idx] = cn;
            if ((t == 0) || (t < sl_s[b])) lc_s[idx] = cn;
            hn[b * NH + j0 + col] = hv;
        }
        __threadfence();
        grid_barrier();
    }

    // ---------------- epilogue: emit last_c ----------------
    #pragma unroll
    for (int q = 0; q < 4; ++q) {
        int idx = q * NTHR + tid;
        int b = idx >> 3, col = idx & 7;
        out[b * NH + j0 + col] = lc_s[idx];
    }
}

extern "C" void kernel_launch(void* const* d_in, const int* in_sizes, int n_in,
                              void* d_out, int out_size)
{
    const int*   tokens = (const int*)d_in[0];
    const int*   seqlen = (const int*)d_in[1];
    const float* emb    = (const float*)d_in[2];
    const float* W_ih   = (const float*)d_in[3];
    const float* W_hh   = (const float*)d_in[4];
    const float* b_ih   = (const float*)d_in[5];
    const float* b_hh   = (const float*)d_in[6];
    float*       out    = (float*)d_out;

    cudaFuncSetAttribute(lstm_persistent,
                         cudaFuncAttributeMaxDynamicSharedMemorySize, SMEM_BYTES);
    lstm_persistent<<<NCTA, NTHR, SMEM_BYTES>>>(tokens, seqlen, emb, W_ih, W_hh,
                                                b_ih, b_hh, out);
}

// round 9
// speedup vs baseline: 1.0459x; 1.0038x over previous
#include <cuda_runtime.h>

// LSTM featurizer: T=1024 steps, B=64, V=256, E=256, H=1024.
// Persistent kernel: 128 CTAs (one per SM), each CTA owns 8 hidden columns
// (=> 32 gate rows: i/f/g/o x 8). W_hh slice (128KB) and Gx lookup table slice
// (32KB) live in SMEM for the whole run. h ping-pongs in gmem (L2-resident),
// steps separated by a sense-reversing grid barrier.

static constexpr int T_STEPS = 1024;
static constexpr int NB      = 64;    // batch
static constexpr int NV      = 256;   // vocab
static constexpr int NE      = 256;   // embed dim
static constexpr int NH      = 1024;  // hidden
static constexpr int NCTA    = 128;
static constexpr int NTHR    = 128;

typedef unsigned long long ull;

__device__ float    g_h[2][NB][NH];   // ping-pong hidden state
__device__ unsigned g_epoch;          // zero-init at module load
__device__ unsigned g_count;

// ---- packed f32x2 FMA (Blackwell FFMA2) ----
__device__ __forceinline__ void fma2(ull& acc, ull a, ull b) {
    asm("fma.rn.f32x2 %0, %1, %2, %0;" : "+l"(acc) : "l"(a), "l"(b));
}
__device__ __forceinline__ float2 unpack2(ull v) {
    float2 r;
    asm("mov.b64 {%0, %1}, %2;" : "=f"(r.x), "=f"(r.y) : "l"(v));
    return r;
}
__device__ __forceinline__ float fast_sigmoid(float x) {
    return __fdividef(1.f, 1.f + __expf(-x));
}
__device__ __forceinline__ float fast_tanh(float x) {
    x = fmaxf(x, -44.f);                 // keep __expf finite (avoid inf/inf)
    float e = __expf(-2.f * x);
    return __fdividef(1.f - e, 1.f + e);
}

__device__ __forceinline__ void grid_barrier() {
    __syncthreads();
    if (threadIdx.x == 0) {
        unsigned e = *((volatile unsigned*)&g_epoch);
        unsigned a = atomicAdd(&g_count, 1);
        if (a == NCTA - 1) {
            *((volatile unsigned*)&g_count) = 0;
            __threadfence();
            atomicAdd(&g_epoch, 1);
        } else {
            while (*((volatile unsigned*)&g_epoch) == e) { __nanosleep(64); }
        }
    }
    __syncthreads();
}

// SMEM layout (floats):
//   W_s   : 32*1024 + 16   (row r at r*1024 + (r>>3)*4 -> conflict-free 16B LDS)
//   Gx_s  : 256*32
//   psum  : 4*64*32        (reused as W_ih^T staging in prologue)
//   c_s   : 512, lc_s : 512, tok_s : 64 (int), sl_s : 64 (int)
static constexpr int W_S_FLOATS  = 32 * 1024 + 16;
static constexpr int GX_FLOATS   = NV * 32;
static constexpr int PSUM_FLOATS = 4 * NB * 32;
static constexpr int SMEM_FLOATS = W_S_FLOATS + GX_FLOATS + PSUM_FLOATS + 512 + 512 + 128;
static constexpr int SMEM_BYTES  = SMEM_FLOATS * 4;

__global__ void __launch_bounds__(NTHR, 1)
lstm_persistent(const int* __restrict__ tokens, const int* __restrict__ seq_len,
                const float* __restrict__ emb, const float* __restrict__ W_ih,
                const float* __restrict__ W_hh, const float* __restrict__ b_ih,
                const float* __restrict__ b_hh, float* __restrict__ out)
{
    extern __shared__ float smem[];
    float* W_s   = smem;
    float* Gx_s  = W_s  + W_S_FLOATS;
    float* psum  = Gx_s + GX_FLOATS;      // also W_ih^T staging in prologue
    float* c_s   = psum + PSUM_FLOATS;
    float* lc_s  = c_s  + 512;
    int*   tok_s = (int*)(lc_s + 512);
    int*   sl_s  = tok_s + 64;

    const int tid  = threadIdx.x;
    const int cta  = blockIdx.x;
    const int j0   = cta * 8;             // this CTA's hidden columns [j0, j0+8)
    const int warp = tid >> 5;
    const int lane = tid & 31;

    // ---------------- prologue ----------------
    // 1) W_hh slice -> SMEM (rows r=0..31: gate=r>>3, col=r&7)
    for (int idx = tid; idx < 32 * NH; idx += NTHR) {
        int r = idx >> 10, k = idx & 1023;
        int grow = (r >> 3) * NH + j0 + (r & 7);
        W_s[r * 1024 + (r >> 3) * 4 + k] = W_hh[grow * NH + k];
    }
    // 2) W_ih^T slice -> psum area: [e][32]
    for (int idx = tid; idx < 32 * NE; idx += NTHR) {
        int r = idx >> 8, e = idx & 255;
        int grow = (r >> 3) * NH + j0 + (r & 7);
        psum[e * 32 + r] = W_ih[grow * NE + e];
    }
    // 3) zero h0 slice + local cell state; stage seq_len
    for (int idx = tid; idx < NB * 8; idx += NTHR) {
        int b = idx >> 3, col = idx & 7;
        g_h[0][b][j0 + col] = 0.f;
        c_s[idx]  = 0.f;
        lc_s[idx] = 0.f;
    }
    if (tid < NB) sl_s[tid] = seq_len[tid];
    __syncthreads();

    // 4) Gx[v][r] = b_ih+b_hh + emb[v] . W_ih[row(r)]  (warp w: v = w,w+4,..., lane = r)
    {
        int grow   = (lane >> 3) * NH + j0 + (lane & 7);
        float bias = b_ih[grow] + b_hh[grow];
        for (int v = warp; v < NV; v += 4) {
            const float4* ev = (const float4*)(emb + v * NE);
            float s = 0.f;
            #pragma unroll 8
            for (int e4 = 0; e4 < NE / 4; ++e4) {
                float4 e = __ldg(ev + e4);
                int eb = e4 * 4;
                s += e.x * psum[(eb + 0) * 32 + lane];
                s += e.y * psum[(eb + 1) * 32 + lane];
                s += e.z * psum[(eb + 2) * 32 + lane];
                s += e.w * psum[(eb + 3) * 32 + lane];
            }
            Gx_s[v * 32 + lane] = s + bias;
        }
    }
    __threadfence();
    grid_barrier();

    // ---------------- main recurrence ----------------
    // thread tile: 8 batches (bg) x 8 gate rows (rg), warp owns k-slice of 256
    const int bg = lane >> 2;
    const int rg = lane & 3;
    const int kbase = warp * 256;

    for (int t = 0; t < T_STEPS; ++t) {
        const float* hp = &g_h[t & 1][0][0];
        float*       hn = &g_h[(t + 1) & 1][0][0];
        if (tid < NB) tok_s[tid] = tokens[t * NB + tid];

        ull acc[8][8];
        #pragma unroll
        for (int i = 0; i < 8; ++i)
            #pragma unroll
            for (int j = 0; j < 8; ++j) acc[i][j] = 0ull;

        const float* hbase = hp  + (bg * 8) * NH + kbase;
        const float* wbase = W_s + (rg * 8) * 1024 + rg * 4 + kbase;

        longlong2 ha[8], hb[8];
        #pragma unroll
        for (int i = 0; i < 8; ++i)
            ha[i] = __ldcg((const longlong2*)(hbase + i * NH));

        #pragma unroll 1
        for (int k4 = 0; k4 < 64; k4 += 2) {
            #pragma unroll
            for (int i = 0; i < 8; ++i)
                hb[i] = __ldcg((const longlong2*)(hbase + i * NH + (k4 + 1) * 4));
            #pragma unroll
            for (int j = 0; j < 8; ++j) {
                longlong2 wv = *(const longlong2*)(wbase + j * 1024 + k4 * 4);
                #pragma unroll
                for (int i = 0; i < 8; ++i) {
                    fma2(acc[i][j], (ull)ha[i].x, (ull)wv.x);
                    fma2(acc[i][j], (ull)ha[i].y, (ull)wv.y);
                }
            }
            if (k4 + 2 < 64) {
                #pragma unroll
                for (int i = 0; i < 8; ++i)
                    ha[i] = __ldcg((const longlong2*)(hbase + i * NH + (k4 + 2) * 4));
            }
            #pragma unroll
            for (int j = 0; j < 8; ++j) {
                longlong2 wv = *(const longlong2*)(wbase + j * 1024 + (k4 + 1) * 4);
                #pragma unroll
                for (int i = 0; i < 8; ++i) {
                    fma2(acc[i][j], (ull)hb[i].x, (ull)wv.x);
                    fma2(acc[i][j], (ull)hb[i].y, (ull)wv.y);
                }
            }
        }

        // partial sums -> SMEM
        #pragma unroll
        for (int i = 0; i < 8; ++i) {
            int b = bg * 8 + i;
            #pragma unroll
            for (int j = 0; j < 8; ++j) {
                float2 f = unpack2(acc[i][j]);
                psum[warp * 2048 + b * 32 + rg * 8 + j] = f.x + f.y;
            }
        }
        __syncthreads();

        // reduce across 4 k-slice warps + gate nonlinearities; 4 (b,col) per thread
        #pragma unroll
        for (int q = 0; q < 4; ++q) {
            int idx = q * NTHR + tid;
            int b = idx >> 3, col = idx & 7;
            float gi = 0.f, gf = 0.f, gg = 0.f, go = 0.f;
            #pragma unroll
            for (int w = 0; w < 4; ++w) {
                const float* pp = psum + w * 2048 + b * 32 + col;
                gi += pp[0]; gf += pp[8]; gg += pp[16]; go += pp[24];
            }
            const float* gx = Gx_s + tok_s[b] * 32 + col;
            gi += gx[0]; gf += gx[8]; gg += gx[16]; go += gx[24];

            float c_old = c_s[idx];
            float cn = fast_sigmoid(gf) * c_old + fast_sigmoid(gi) * fast_tanh(gg);
            float hv = fast_sigmoid(go) * fast_tanh(cn);
            c_s[idx] = cn;
            if ((t == 0) || (t < sl_s[b])) lc_s[idx] = cn;
            hn[b * NH + j0 + col] = hv;
        }
        __threadfence();
        grid_barrier();
    }

    // ---------------- epilogue: emit last_c ----------------
    #pragma unroll
    for (int q = 0; q < 4; ++q) {
        int idx = q * NTHR + tid;
        int b = idx >> 3, col = idx & 7;
        out[b * NH + j0 + col] = lc_s[idx];
    }
}

extern "C" void kernel_launch(void* const* d_in, const int* in_sizes, int n_in,
                              void* d_out, int out_size)
{
    const int*   tokens = (const int*)d_in[0];
    const int*   seqlen = (const int*)d_in[1];
    const float* emb    = (const float*)d_in[2];
    const float* W_ih   = (const float*)d_in[3];
    const float* W_hh   = (const float*)d_in[4];
    const float* b_ih   = (const float*)d_in[5];
    const float* b_hh   = (const float*)d_in[6];
    float*       out    = (float*)d_out;

    cudaFuncSetAttribute(lstm_persistent,
                         cudaFuncAttributeMaxDynamicSharedMemorySize, SMEM_BYTES);
    lstm_persistent<<<NCTA, NTHR, SMEM_BYTES>>>(tokens, seqlen, emb, W_ih, W_hh,
                                                b_ih, b_hh, out);
}